// round 6
// baseline (speedup 1.0000x reference)
#include <cuda_runtime.h>
#include <cuda_bf16.h>
#include <cstdint>

// Problem constants (1, 768, 128, 128)
#define C_DIM 768
#define N_DIM 16384

// ---------------- GEMM tiling (bf16 mma.sync m16n8k16) ----------------
#define BM 128            // CTA tile M
#define BN 256            // CTA tile N
#define KC 64             // K per chunk = 128 bytes/row
#define NCHUNK (C_DIM / KC)   // 12
#define NSTAGE 4

#define A_STAGE_BYTES (BM * 128)              // 16384
#define B_STAGE_BYTES (BN * 128)              // 32768
#define STAGE_BYTES (A_STAGE_BYTES + B_STAGE_BYTES)   // 49152
#define SMAX_OFF (NSTAGE * STAGE_BYTES)       // 196608
#define SMEM_TOTAL (SMAX_OFF + 512)

// ---------------- scratch (no allocations allowed) ----------------
__device__ float g_inv_r[N_DIM];
__device__ float g_inv_s[N_DIM];
__device__ __nv_bfloat16 g_A[(size_t)N_DIM * C_DIM];   // normalized F_r, [n][c]
__device__ __nv_bfloat16 g_B[(size_t)N_DIM * C_DIM];   // normalized F_s, [m][c]
__device__ unsigned int g_rowmax[N_DIM];               // monotonic float keys

__device__ __forceinline__ unsigned int fkey(float f) {
    unsigned int u = __float_as_uint(f);
    return (u & 0x80000000u) ? ~u : (u | 0x80000000u);
}
__device__ __forceinline__ uint32_t smem_u32(const void* p) {
    return (uint32_t)__cvta_generic_to_shared(p);
}

#define LDSM4(r0, r1, r2, r3, addr) \
    asm volatile("ldmatrix.sync.aligned.m8n8.x4.shared.b16 {%0,%1,%2,%3}, [%4];" \
                 : "=r"(r0), "=r"(r1), "=r"(r2), "=r"(r3) : "r"(addr))

// ---------------- init row maxes ----------------
__global__ void init_rowmax_kernel() {
    int i = blockIdx.x * blockDim.x + threadIdx.x;
    if (i < N_DIM) g_rowmax[i] = 0u;
}

// ---------------- inverse column norms: X is [C][N], norm over C ----------------
__global__ void colnorm_kernel(const float* __restrict__ X, int which) {
    __shared__ float red[256];
    int tid = threadIdx.x;
    int n = blockIdx.x * 64 + (tid & 63);
    int part = tid >> 6;
    const int CP = C_DIM / 4;
    const float* p = X + (size_t)part * CP * N_DIM + n;
    float s = 0.f;
    #pragma unroll 4
    for (int c = 0; c < CP; ++c) {
        float v = p[(size_t)c * N_DIM];
        s += v * v;
    }
    red[tid] = s;
    __syncthreads();
    if (tid < 64) {
        float t = red[tid] + red[tid + 64] + red[tid + 128] + red[tid + 192];
        float inv = 1.0f / fmaxf(sqrtf(t), 1e-12f);
        if (which) g_inv_s[n] = inv; else g_inv_r[n] = inv;
    }
}

// -------- transpose + normalize + bf16: [C][N] -> [N][C], 64x64 tiles, float4 ----
__global__ void __launch_bounds__(256) transpose_scale_kernel(const float* __restrict__ X,
                                                              int which) {
    __shared__ float tf[64][65];
    const float* inv = which ? g_inv_s : g_inv_r;
    __nv_bfloat16* T = which ? g_B : g_A;
    int n0 = blockIdx.x * 64;
    int c0 = blockIdx.y * 64;
    int t = threadIdx.x;

    #pragma unroll
    for (int i = 0; i < 4; ++i) {
        int idx = i * 256 + t;
        int row = idx >> 4;            // c offset 0..63
        int v4 = idx & 15;             // float4 index within row
        float4 v = *(const float4*)(X + (size_t)(c0 + row) * N_DIM + n0 + v4 * 4);
        tf[row][v4 * 4 + 0] = v.x;
        tf[row][v4 * 4 + 1] = v.y;
        tf[row][v4 * 4 + 2] = v.z;
        tf[row][v4 * 4 + 3] = v.w;
    }
    __syncthreads();

    #pragma unroll
    for (int j = 0; j < 8; ++j) {
        int idx = j * 256 + t;
        int nn = idx >> 5;             // n offset 0..63
        int p = idx & 31;              // bf16 pair within the 64 c's
        int n = n0 + nn;
        float iv = inv[n];
        __nv_bfloat162 h = __floats2bfloat162_rn(tf[2 * p][nn] * iv, tf[2 * p + 1][nn] * iv);
        *(__nv_bfloat162*)(T + (size_t)n * C_DIM + c0 + 2 * p) = h;
    }
}

// ---------------- fused GEMM + row-max ----------------
// smem rows of 128B; 16B chunk ch swizzled: off = row*128 + ((ch ^ (row&7)) << 4)
__device__ __forceinline__ void load_stage(uint32_t smem_base, int stage, int chunk,
                                           const __nv_bfloat16* gA,
                                           const __nv_bfloat16* gB, int tid) {
    uint32_t sA = smem_base + stage * STAGE_BYTES;
    uint32_t sB = sA + A_STAGE_BYTES;
    const __nv_bfloat16* srcA = gA + chunk * KC;
    const __nv_bfloat16* srcB = gB + chunk * KC;
    #pragma unroll
    for (int i = 0; i < 4; ++i) {            // A: 128 rows x 8 chunks = 1024
        int c = i * 256 + tid;
        int row = c >> 3, ch = c & 7;
        uint32_t off = row * 128 + ((ch ^ (row & 7)) << 4);
        const __nv_bfloat16* p = srcA + (size_t)row * C_DIM + ch * 8;
        asm volatile("cp.async.cg.shared.global [%0], [%1], 16;" :: "r"(sA + off), "l"(p));
    }
    #pragma unroll
    for (int i = 0; i < 8; ++i) {            // B: 256 rows x 8 chunks = 2048
        int c = i * 256 + tid;
        int row = c >> 3, ch = c & 7;
        uint32_t off = row * 128 + ((ch ^ (row & 7)) << 4);
        const __nv_bfloat16* p = srcB + (size_t)row * C_DIM + ch * 8;
        asm volatile("cp.async.cg.shared.global [%0], [%1], 16;" :: "r"(sB + off), "l"(p));
    }
    asm volatile("cp.async.commit_group;");
}

__global__ void __launch_bounds__(256, 1) nnfm_gemm_hmma() {
    extern __shared__ __align__(1024) char smem[];
    uint32_t smem_base = smem_u32(smem);
    unsigned int* smax = (unsigned int*)(smem + SMAX_OFF);

    int tid = threadIdx.x;
    int wid = tid >> 5;
    int lane = tid & 31;
    int tileM = blockIdx.y, tileN = blockIdx.x;

    const __nv_bfloat16* gA = g_A + (size_t)tileM * BM * C_DIM;
    const __nv_bfloat16* gB = g_B + (size_t)tileN * BN * C_DIM;

    // warp grid: 2 (M) x 4 (N); warp tile 64x64 = 4x8 frags of m16n8
    int mb = (wid >> 2) * 64;
    int nb = (wid & 3) * 64;

    // ldmatrix lane addresses with swizzle folded
    int grpRowA = (lane & 7) + ((lane >> 3) & 1) * 8;
    uint32_t aKbit = (uint32_t)(lane >> 4) << 4;
    uint32_t baseA[4];
    #pragma unroll
    for (int mi = 0; mi < 4; ++mi) {
        int r = mb + mi * 16 + grpRowA;
        baseA[mi] = (smem_base + r * 128 + ((r & 7) << 4)) ^ aKbit;
    }
    int grpRowB = (lane & 7) + ((lane >> 4) << 3);
    uint32_t bKbit = (uint32_t)((lane >> 3) & 1) << 4;
    uint32_t baseB[4];
    #pragma unroll
    for (int p = 0; p < 4; ++p) {
        int r = nb + p * 16 + grpRowB;
        baseB[p] = (smem_base + A_STAGE_BYTES + r * 128 + ((r & 7) << 4)) ^ bKbit;
    }

    float acc[4][8][4];
    #pragma unroll
    for (int mi = 0; mi < 4; ++mi)
        #pragma unroll
        for (int ni = 0; ni < 8; ++ni)
            #pragma unroll
            for (int q = 0; q < 4; ++q) acc[mi][ni][q] = 0.f;

    #pragma unroll
    for (int s = 0; s < NSTAGE - 1; ++s) load_stage(smem_base, s, s, gA, gB, tid);

    uint32_t a[2][4][4], b[2][8][2];   // double-buffered fragments

    for (int k = 0; k < NCHUNK; ++k) {
        int st = k & (NSTAGE - 1);
        uint32_t stOff = st * STAGE_BYTES;
        asm volatile("cp.async.wait_group %0;" :: "n"(NSTAGE - 2));
        __syncthreads();

        // prefetch kstep 0 fragments
        #pragma unroll
        for (int mi = 0; mi < 4; ++mi)
            LDSM4(a[0][mi][0], a[0][mi][1], a[0][mi][2], a[0][mi][3], baseA[mi] + stOff);
        #pragma unroll
        for (int p = 0; p < 4; ++p)
            LDSM4(b[0][2*p][0], b[0][2*p][1], b[0][2*p+1][0], b[0][2*p+1][1],
                  baseB[p] + stOff);

        // issue next gmem stage while fragments are in flight
        if (k + NSTAGE - 1 < NCHUNK)
            load_stage(smem_base, (k + NSTAGE - 1) & (NSTAGE - 1), k + NSTAGE - 1, gA, gB, tid);
        else
            asm volatile("cp.async.commit_group;");   // keep group count stable

        #pragma unroll
        for (int ki = 0; ki < 4; ++ki) {
            int cur = ki & 1, nxt = cur ^ 1;
            if (ki < 3) {                              // prefetch kstep ki+1
                uint32_t kx = (uint32_t)(ki + 1) << 5;
                #pragma unroll
                for (int mi = 0; mi < 4; ++mi)
                    LDSM4(a[nxt][mi][0], a[nxt][mi][1], a[nxt][mi][2], a[nxt][mi][3],
                          (baseA[mi] + stOff) ^ kx);
                #pragma unroll
                for (int p = 0; p < 4; ++p)
                    LDSM4(b[nxt][2*p][0], b[nxt][2*p][1], b[nxt][2*p+1][0], b[nxt][2*p+1][1],
                          (baseB[p] + stOff) ^ kx);
            }
            #pragma unroll
            for (int mi = 0; mi < 4; ++mi)
                #pragma unroll
                for (int ni = 0; ni < 8; ++ni) {
                    float* c = acc[mi][ni];
                    asm volatile(
                        "mma.sync.aligned.m16n8k16.row.col.f32.bf16.bf16.f32 "
                        "{%0,%1,%2,%3}, {%4,%5,%6,%7}, {%8,%9}, {%0,%1,%2,%3};"
                        : "+f"(c[0]), "+f"(c[1]), "+f"(c[2]), "+f"(c[3])
                        : "r"(a[cur][mi][0]), "r"(a[cur][mi][1]),
                          "r"(a[cur][mi][2]), "r"(a[cur][mi][3]),
                          "r"(b[cur][ni][0]), "r"(b[cur][ni][1]));
                }
        }
    }

    // ---- epilogue: per-row max of this 128x256 tile ----
    __syncthreads();
    if (tid < BM) smax[tid] = 0u;
    __syncthreads();

    #pragma unroll
    for (int mi = 0; mi < 4; ++mi) {
        float m0 = -3.402823466e38f, m1 = -3.402823466e38f;
        #pragma unroll
        for (int ni = 0; ni < 8; ++ni) {
            m0 = fmaxf(m0, fmaxf(acc[mi][ni][0], acc[mi][ni][1]));
            m1 = fmaxf(m1, fmaxf(acc[mi][ni][2], acc[mi][ni][3]));
        }
        m0 = fmaxf(m0, __shfl_xor_sync(0xffffffffu, m0, 1));
        m0 = fmaxf(m0, __shfl_xor_sync(0xffffffffu, m0, 2));
        m1 = fmaxf(m1, __shfl_xor_sync(0xffffffffu, m1, 1));
        m1 = fmaxf(m1, __shfl_xor_sync(0xffffffffu, m1, 2));
        if ((lane & 3) == 0) {
            int r = mb + mi * 16 + (lane >> 2);
            atomicMax(&smax[r], fkey(m0));
            atomicMax(&smax[r + 8], fkey(m1));
        }
    }
    __syncthreads();
    if (tid < BM) atomicMax(&g_rowmax[tileM * BM + tid], smax[tid]);
}

// ---------------- final: loss = mean(1 - rowmax) ----------------
__global__ void final_reduce_kernel(float* __restrict__ out) {
    __shared__ float red[256];
    int tid = threadIdx.x;
    float s = 0.f;
    for (int i = tid; i < N_DIM; i += 256) {
        unsigned int key = g_rowmax[i];
        float f = (key & 0x80000000u) ? __uint_as_float(key & 0x7FFFFFFFu)
                                      : __uint_as_float(~key);
        s += 1.0f - f;
    }
    red[tid] = s;
    __syncthreads();
    for (int off = 128; off > 0; off >>= 1) {
        if (tid < off) red[tid] += red[tid + off];
        __syncthreads();
    }
    if (tid == 0) out[0] = red[0] / (float)N_DIM;
}

// ---------------- launch ----------------
extern "C" void kernel_launch(void* const* d_in, const int* in_sizes, int n_in,
                              void* d_out, int out_size) {
    const float* F_r = (const float*)d_in[0];
    const float* F_s = (const float*)d_in[1];

    cudaFuncSetAttribute(nnfm_gemm_hmma, cudaFuncAttributeMaxDynamicSharedMemorySize, SMEM_TOTAL);

    init_rowmax_kernel<<<N_DIM / 256, 256>>>();
    colnorm_kernel<<<N_DIM / 64, 256>>>(F_r, 0);
    colnorm_kernel<<<N_DIM / 64, 256>>>(F_s, 1);

    dim3 tg(N_DIM / 64, C_DIM / 64);   // 256 x 12
    transpose_scale_kernel<<<tg, 256>>>(F_r, 0);
    transpose_scale_kernel<<<tg, 256>>>(F_s, 1);

    dim3 gg(N_DIM / BN, N_DIM / BM);   // 64 x 128
    nnfm_gemm_hmma<<<gg, 256, SMEM_TOTAL>>>();

    final_reduce_kernel<<<1, 256>>>((float*)d_out);
}

// round 7
// speedup vs baseline: 1.0081x; 1.0081x over previous
#include <cuda_runtime.h>
#include <cuda_fp16.h>
#include <cstdint>

// Problem constants (1, 768, 128, 128)
#define C_DIM 768
#define N_DIM 16384

// ---------------- GEMM tiling (fp16 mma.sync m16n8k16, f16 accum) ----------------
#define BM 128            // CTA tile M
#define BN 256            // CTA tile N
#define KC 64             // K per chunk = 128 bytes/row
#define NCHUNK (C_DIM / KC)   // 12
#define NSTAGE 4

#define A_STAGE_BYTES (BM * 128)              // 16384
#define B_STAGE_BYTES (BN * 128)              // 32768
#define STAGE_BYTES (A_STAGE_BYTES + B_STAGE_BYTES)   // 49152
#define SMAX_OFF (NSTAGE * STAGE_BYTES)       // 196608
#define SMEM_TOTAL (SMAX_OFF + 512)

// ---------------- scratch (no allocations allowed) ----------------
__device__ float g_inv_r[N_DIM];
__device__ float g_inv_s[N_DIM];
__device__ __half g_A[(size_t)N_DIM * C_DIM];   // normalized F_r, [n][c]
__device__ __half g_B[(size_t)N_DIM * C_DIM];   // normalized F_s, [m][c]
__device__ unsigned int g_rowmax[N_DIM];        // monotonic float keys

__device__ __forceinline__ unsigned int fkey(float f) {
    unsigned int u = __float_as_uint(f);
    return (u & 0x80000000u) ? ~u : (u | 0x80000000u);
}
__device__ __forceinline__ uint32_t smem_u32(const void* p) {
    return (uint32_t)__cvta_generic_to_shared(p);
}

#define LDSM4(r0, r1, r2, r3, addr) \
    asm volatile("ldmatrix.sync.aligned.m8n8.x4.shared.b16 {%0,%1,%2,%3}, [%4];" \
                 : "=r"(r0), "=r"(r1), "=r"(r2), "=r"(r3) : "r"(addr))

// ---------------- init row maxes ----------------
__global__ void init_rowmax_kernel() {
    int i = blockIdx.x * blockDim.x + threadIdx.x;
    if (i < N_DIM) g_rowmax[i] = 0u;
}

// ---------------- inverse column norms: X is [C][N], norm over C ----------------
__global__ void colnorm_kernel(const float* __restrict__ X, int which) {
    __shared__ float red[256];
    int tid = threadIdx.x;
    int n = blockIdx.x * 64 + (tid & 63);
    int part = tid >> 6;
    const int CP = C_DIM / 4;
    const float* p = X + (size_t)part * CP * N_DIM + n;
    float s = 0.f;
    #pragma unroll 4
    for (int c = 0; c < CP; ++c) {
        float v = p[(size_t)c * N_DIM];
        s += v * v;
    }
    red[tid] = s;
    __syncthreads();
    if (tid < 64) {
        float t = red[tid] + red[tid + 64] + red[tid + 128] + red[tid + 192];
        float inv = 1.0f / fmaxf(sqrtf(t), 1e-12f);
        if (which) g_inv_s[n] = inv; else g_inv_r[n] = inv;
    }
}

// -------- transpose + normalize + fp16: [C][N] -> [N][C], 64x64 tiles, float4 ----
__global__ void __launch_bounds__(256) transpose_scale_kernel(const float* __restrict__ X,
                                                              int which) {
    __shared__ float tf[64][65];
    const float* inv = which ? g_inv_s : g_inv_r;
    __half* T = which ? g_B : g_A;
    int n0 = blockIdx.x * 64;
    int c0 = blockIdx.y * 64;
    int t = threadIdx.x;

    #pragma unroll
    for (int i = 0; i < 4; ++i) {
        int idx = i * 256 + t;
        int row = idx >> 4;            // c offset 0..63
        int v4 = idx & 15;             // float4 index within row
        float4 v = *(const float4*)(X + (size_t)(c0 + row) * N_DIM + n0 + v4 * 4);
        tf[row][v4 * 4 + 0] = v.x;
        tf[row][v4 * 4 + 1] = v.y;
        tf[row][v4 * 4 + 2] = v.z;
        tf[row][v4 * 4 + 3] = v.w;
    }
    __syncthreads();

    #pragma unroll
    for (int j = 0; j < 8; ++j) {
        int idx = j * 256 + t;
        int nn = idx >> 5;             // n offset 0..63
        int p = idx & 31;              // fp16 pair within the 64 c's
        int n = n0 + nn;
        float iv = inv[n];
        __half2 h = __floats2half2_rn(tf[2 * p][nn] * iv, tf[2 * p + 1][nn] * iv);
        *(__half2*)(T + (size_t)n * C_DIM + c0 + 2 * p) = h;
    }
}

// ---------------- fused GEMM + row-max ----------------
// smem rows of 128B; 16B chunk ch swizzled: off = row*128 + ((ch ^ (row&7)) << 4)
__device__ __forceinline__ void load_stage(uint32_t smem_base, int stage, int chunk,
                                           const __half* gA,
                                           const __half* gB, int tid) {
    uint32_t sA = smem_base + stage * STAGE_BYTES;
    uint32_t sB = sA + A_STAGE_BYTES;
    const __half* srcA = gA + chunk * KC;
    const __half* srcB = gB + chunk * KC;
    #pragma unroll
    for (int i = 0; i < 4; ++i) {            // A: 128 rows x 8 chunks = 1024
        int c = i * 256 + tid;
        int row = c >> 3, ch = c & 7;
        uint32_t off = row * 128 + ((ch ^ (row & 7)) << 4);
        const __half* p = srcA + (size_t)row * C_DIM + ch * 8;
        asm volatile("cp.async.cg.shared.global [%0], [%1], 16;" :: "r"(sA + off), "l"(p));
    }
    #pragma unroll
    for (int i = 0; i < 8; ++i) {            // B: 256 rows x 8 chunks = 2048
        int c = i * 256 + tid;
        int row = c >> 3, ch = c & 7;
        uint32_t off = row * 128 + ((ch ^ (row & 7)) << 4);
        const __half* p = srcB + (size_t)row * C_DIM + ch * 8;
        asm volatile("cp.async.cg.shared.global [%0], [%1], 16;" :: "r"(sB + off), "l"(p));
    }
    asm volatile("cp.async.commit_group;");
}

__global__ void __launch_bounds__(256, 1) nnfm_gemm_hmma() {
    extern __shared__ __align__(1024) char smem[];
    uint32_t smem_base = smem_u32(smem);
    unsigned int* smax = (unsigned int*)(smem + SMAX_OFF);

    int tid = threadIdx.x;
    int wid = tid >> 5;
    int lane = tid & 31;
    int tileM = blockIdx.y, tileN = blockIdx.x;

    const __half* gA = g_A + (size_t)tileM * BM * C_DIM;
    const __half* gB = g_B + (size_t)tileN * BN * C_DIM;

    // warp grid: 2 (M) x 4 (N); warp tile 64x64 = 4x8 frags of m16n8
    int mb = (wid >> 2) * 64;
    int nb = (wid & 3) * 64;

    // ldmatrix lane addresses with swizzle folded
    int grpRowA = (lane & 7) + ((lane >> 3) & 1) * 8;
    uint32_t aKbit = (uint32_t)(lane >> 4) << 4;
    uint32_t baseA[4];
    #pragma unroll
    for (int mi = 0; mi < 4; ++mi) {
        int r = mb + mi * 16 + grpRowA;
        baseA[mi] = (smem_base + r * 128 + ((r & 7) << 4)) ^ aKbit;
    }
    int grpRowB = (lane & 7) + ((lane >> 4) << 3);
    uint32_t bKbit = (uint32_t)((lane >> 3) & 1) << 4;
    uint32_t baseB[4];
    #pragma unroll
    for (int p = 0; p < 4; ++p) {
        int r = nb + p * 16 + grpRowB;
        baseB[p] = (smem_base + A_STAGE_BYTES + r * 128 + ((r & 7) << 4)) ^ bKbit;
    }

    uint32_t acc[4][8][2];                   // f16x2 accumulators
    #pragma unroll
    for (int mi = 0; mi < 4; ++mi)
        #pragma unroll
        for (int ni = 0; ni < 8; ++ni) {
            acc[mi][ni][0] = 0u;
            acc[mi][ni][1] = 0u;
        }

    #pragma unroll
    for (int s = 0; s < NSTAGE - 1; ++s) load_stage(smem_base, s, s, gA, gB, tid);

    uint32_t a[2][4][4], b[2][8][2];         // double-buffered fragments

    for (int k = 0; k < NCHUNK; ++k) {
        int st = k & (NSTAGE - 1);
        uint32_t stOff = st * STAGE_BYTES;
        asm volatile("cp.async.wait_group %0;" :: "n"(NSTAGE - 2));
        __syncthreads();

        // prefetch kstep 0 fragments
        #pragma unroll
        for (int mi = 0; mi < 4; ++mi)
            LDSM4(a[0][mi][0], a[0][mi][1], a[0][mi][2], a[0][mi][3], baseA[mi] + stOff);
        #pragma unroll
        for (int p = 0; p < 4; ++p)
            LDSM4(b[0][2*p][0], b[0][2*p][1], b[0][2*p+1][0], b[0][2*p+1][1],
                  baseB[p] + stOff);

        // issue next gmem stage while fragments are in flight
        if (k + NSTAGE - 1 < NCHUNK)
            load_stage(smem_base, (k + NSTAGE - 1) & (NSTAGE - 1), k + NSTAGE - 1, gA, gB, tid);
        else
            asm volatile("cp.async.commit_group;");   // keep group count stable

        #pragma unroll
        for (int ki = 0; ki < 4; ++ki) {
            int cur = ki & 1, nxt = cur ^ 1;
            if (ki < 3) {                              // prefetch kstep ki+1
                uint32_t kx = (uint32_t)(ki + 1) << 5;
                #pragma unroll
                for (int mi = 0; mi < 4; ++mi)
                    LDSM4(a[nxt][mi][0], a[nxt][mi][1], a[nxt][mi][2], a[nxt][mi][3],
                          (baseA[mi] + stOff) ^ kx);
                #pragma unroll
                for (int p = 0; p < 4; ++p)
                    LDSM4(b[nxt][2*p][0], b[nxt][2*p][1], b[nxt][2*p+1][0], b[nxt][2*p+1][1],
                          (baseB[p] + stOff) ^ kx);
            }
            #pragma unroll
            for (int mi = 0; mi < 4; ++mi)
                #pragma unroll
                for (int ni = 0; ni < 8; ++ni) {
                    uint32_t* c = acc[mi][ni];
                    asm volatile(
                        "mma.sync.aligned.m16n8k16.row.col.f16.f16.f16.f16 "
                        "{%0,%1}, {%2,%3,%4,%5}, {%6,%7}, {%0,%1};"
                        : "+r"(c[0]), "+r"(c[1])
                        : "r"(a[cur][mi][0]), "r"(a[cur][mi][1]),
                          "r"(a[cur][mi][2]), "r"(a[cur][mi][3]),
                          "r"(b[cur][ni][0]), "r"(b[cur][ni][1]));
                }
        }
    }

    // ---- epilogue: per-row max of this 128x256 tile ----
    __syncthreads();
    if (tid < BM) smax[tid] = 0u;
    __syncthreads();

    #pragma unroll
    for (int mi = 0; mi < 4; ++mi) {
        __half2 h0 = __float2half2_rn(-60000.0f);
        __half2 h1 = __float2half2_rn(-60000.0f);
        #pragma unroll
        for (int ni = 0; ni < 8; ++ni) {
            h0 = __hmax2(h0, *(__half2*)&acc[mi][ni][0]);   // row = mb+mi*16+lane/4
            h1 = __hmax2(h1, *(__half2*)&acc[mi][ni][1]);   // row + 8
        }
        float m0 = fmaxf(__low2float(h0), __high2float(h0));
        float m1 = fmaxf(__low2float(h1), __high2float(h1));
        m0 = fmaxf(m0, __shfl_xor_sync(0xffffffffu, m0, 1));
        m0 = fmaxf(m0, __shfl_xor_sync(0xffffffffu, m0, 2));
        m1 = fmaxf(m1, __shfl_xor_sync(0xffffffffu, m1, 1));
        m1 = fmaxf(m1, __shfl_xor_sync(0xffffffffu, m1, 2));
        if ((lane & 3) == 0) {
            int r = mb + mi * 16 + (lane >> 2);
            atomicMax(&smax[r], fkey(m0));
            atomicMax(&smax[r + 8], fkey(m1));
        }
    }
    __syncthreads();
    if (tid < BM) atomicMax(&g_rowmax[tileM * BM + tid], smax[tid]);
}

// ---------------- final: loss = mean(1 - rowmax) ----------------
__global__ void final_reduce_kernel(float* __restrict__ out) {
    __shared__ float red[256];
    int tid = threadIdx.x;
    float s = 0.f;
    for (int i = tid; i < N_DIM; i += 256) {
        unsigned int key = g_rowmax[i];
        float f = (key & 0x80000000u) ? __uint_as_float(key & 0x7FFFFFFFu)
                                      : __uint_as_float(~key);
        s += 1.0f - f;
    }
    red[tid] = s;
    __syncthreads();
    for (int off = 128; off > 0; off >>= 1) {
        if (tid < off) red[tid] += red[tid + off];
        __syncthreads();
    }
    if (tid == 0) out[0] = red[0] / (float)N_DIM;
}

// ---------------- launch ----------------
extern "C" void kernel_launch(void* const* d_in, const int* in_sizes, int n_in,
                              void* d_out, int out_size) {
    const float* F_r = (const float*)d_in[0];
    const float* F_s = (const float*)d_in[1];

    cudaFuncSetAttribute(nnfm_gemm_hmma, cudaFuncAttributeMaxDynamicSharedMemorySize, SMEM_TOTAL);

    init_rowmax_kernel<<<N_DIM / 256, 256>>>();
    colnorm_kernel<<<N_DIM / 64, 256>>>(F_r, 0);
    colnorm_kernel<<<N_DIM / 64, 256>>>(F_s, 1);

    dim3 tg(N_DIM / 64, C_DIM / 64);   // 256 x 12
    transpose_scale_kernel<<<tg, 256>>>(F_r, 0);
    transpose_scale_kernel<<<tg, 256>>>(F_s, 1);

    dim3 gg(N_DIM / BN, N_DIM / BM);   // 64 x 128
    nnfm_gemm_hmma<<<gg, 256, SMEM_TOTAL>>>();

    final_reduce_kernel<<<1, 256>>>((float*)d_out);
}

// round 8
// speedup vs baseline: 1.0853x; 1.0766x over previous
#include <cuda_runtime.h>
#include <cuda_fp16.h>
#include <cstdint>

// Problem constants (1, 768, 128, 128)
#define C_DIM 768
#define N_DIM 16384

// ---------------- GEMM tiling (fp16 mma.sync, occ=2) ----------------
#define BM 128
#define BN 128
#define KC 64                 // K per chunk = 128 bytes/row
#define NCHUNK (C_DIM / KC)   // 12
#define NSTAGE 3

#define A_STAGE_BYTES (BM * 128)                       // 16384
#define STAGE_BYTES ((BM + BN) * 128)                  // 32768
#define SMAX_OFF (NSTAGE * STAGE_BYTES)                // 98304
#define SMEM_TOTAL (SMAX_OFF + 512)                    // ~98.8KB -> 2 CTAs/SM

// ---------------- scratch (no allocations allowed) ----------------
__device__ float g_part[2][4][N_DIM];           // partial sum-of-squares
__device__ __half g_A[(size_t)N_DIM * C_DIM];   // normalized F_r, [n][c]
__device__ __half g_B[(size_t)N_DIM * C_DIM];   // normalized F_s, [m][c]
__device__ unsigned int g_rowmax[N_DIM];        // monotonic float keys

__device__ __forceinline__ unsigned int fkey(float f) {
    unsigned int u = __float_as_uint(f);
    return (u & 0x80000000u) ? ~u : (u | 0x80000000u);
}
__device__ __forceinline__ uint32_t smem_u32(const void* p) {
    return (uint32_t)__cvta_generic_to_shared(p);
}

#define LDSM4(r0, r1, r2, r3, addr) \
    asm volatile("ldmatrix.sync.aligned.m8n8.x4.shared.b16 {%0,%1,%2,%3}, [%4];" \
                 : "=r"(r0), "=r"(r1), "=r"(r2), "=r"(r3) : "r"(addr))

// ---------------- init row maxes ----------------
__global__ void init_rowmax_kernel() {
    int i = blockIdx.x * blockDim.x + threadIdx.x;
    if (i < N_DIM) g_rowmax[i] = 0u;
}

// ---- partial column norms: thread owns one n, sums 192 c's (coalesced) ----
__global__ void __launch_bounds__(256) colnorm_part_kernel(const float* __restrict__ X,
                                                           int which) {
    int n = blockIdx.x * 256 + threadIdx.x;
    int part = blockIdx.y;
    const float* p = X + (size_t)part * 192 * N_DIM + n;
    float s = 0.f;
    #pragma unroll 8
    for (int c = 0; c < 192; ++c) {
        float v = p[(size_t)c * N_DIM];
        s += v * v;
    }
    g_part[which][part][n] = s;
}

// -------- transpose + normalize + fp16: [C][N] -> [N][C], 64x64 tiles ----------
__global__ void __launch_bounds__(256) transpose_scale_kernel(const float* __restrict__ X,
                                                              int which) {
    __shared__ float tf[64][65];
    __shared__ float sinv[64];
    __half* T = which ? g_B : g_A;
    int n0 = blockIdx.x * 64;
    int c0 = blockIdx.y * 64;
    int t = threadIdx.x;

    if (t < 64) {
        int n = n0 + t;
        float s = g_part[which][0][n] + g_part[which][1][n]
                + g_part[which][2][n] + g_part[which][3][n];
        sinv[t] = 1.0f / fmaxf(sqrtf(s), 1e-12f);
    }

    #pragma unroll
    for (int i = 0; i < 4; ++i) {
        int idx = i * 256 + t;
        int row = idx >> 4;            // c offset 0..63
        int v4 = idx & 15;             // float4 index within row
        float4 v = *(const float4*)(X + (size_t)(c0 + row) * N_DIM + n0 + v4 * 4);
        tf[row][v4 * 4 + 0] = v.x;
        tf[row][v4 * 4 + 1] = v.y;
        tf[row][v4 * 4 + 2] = v.z;
        tf[row][v4 * 4 + 3] = v.w;
    }
    __syncthreads();

    #pragma unroll
    for (int j = 0; j < 8; ++j) {
        int idx = j * 256 + t;
        int nn = idx >> 5;             // n offset 0..63
        int p = idx & 31;              // fp16 pair within the 64 c's
        float iv = sinv[nn];
        __half2 h = __floats2half2_rn(tf[2 * p][nn] * iv, tf[2 * p + 1][nn] * iv);
        *(__half2*)(T + (size_t)(n0 + nn) * C_DIM + c0 + 2 * p) = h;
    }
}

// ---------------- fused GEMM + row-max ----------------
// smem rows of 128B; 16B chunk ch swizzled: off = row*128 + ((ch ^ (row&7)) << 4)
__device__ __forceinline__ void load_stage(uint32_t smem_base, int stage, int chunk,
                                           const __half* gA,
                                           const __half* gB, int tid) {
    uint32_t sA = smem_base + stage * STAGE_BYTES;
    uint32_t sB = sA + A_STAGE_BYTES;
    const __half* srcA = gA + chunk * KC;
    const __half* srcB = gB + chunk * KC;
    #pragma unroll
    for (int i = 0; i < 4; ++i) {            // A: 128 rows x 8 chunks = 1024
        int c = i * 256 + tid;
        int row = c >> 3, ch = c & 7;
        uint32_t off = row * 128 + ((ch ^ (row & 7)) << 4);
        const __half* p = srcA + (size_t)row * C_DIM + ch * 8;
        asm volatile("cp.async.cg.shared.global [%0], [%1], 16;" :: "r"(sA + off), "l"(p));
    }
    #pragma unroll
    for (int i = 0; i < 4; ++i) {            // B: 128 rows x 8 chunks = 1024
        int c = i * 256 + tid;
        int row = c >> 3, ch = c & 7;
        uint32_t off = row * 128 + ((ch ^ (row & 7)) << 4);
        const __half* p = srcB + (size_t)row * C_DIM + ch * 8;
        asm volatile("cp.async.cg.shared.global [%0], [%1], 16;" :: "r"(sB + off), "l"(p));
    }
    asm volatile("cp.async.commit_group;");
}

__global__ void __launch_bounds__(256, 2) nnfm_gemm_hmma() {
    extern __shared__ __align__(1024) char smem[];
    uint32_t smem_base = smem_u32(smem);
    unsigned int* smax = (unsigned int*)(smem + SMAX_OFF);

    int tid = threadIdx.x;
    int wid = tid >> 5;
    int lane = tid & 31;
    int tileM = blockIdx.y, tileN = blockIdx.x;

    const __half* gA = g_A + (size_t)tileM * BM * C_DIM;
    const __half* gB = g_B + (size_t)tileN * BN * C_DIM;

    // warp grid: 2 (M) x 4 (N); warp tile 64x32 = 4x4 frags of m16n8
    int mb = (wid >> 2) * 64;
    int nb = (wid & 3) * 32;

    // ldmatrix lane addresses with swizzle folded
    int grpRowA = (lane & 7) + ((lane >> 3) & 1) * 8;
    uint32_t aKbit = (uint32_t)(lane >> 4) << 4;
    uint32_t baseA[4];
    #pragma unroll
    for (int mi = 0; mi < 4; ++mi) {
        int r = mb + mi * 16 + grpRowA;
        baseA[mi] = (smem_base + r * 128 + ((r & 7) << 4)) ^ aKbit;
    }
    int grpRowB = (lane & 7) + ((lane >> 4) << 3);
    uint32_t bKbit = (uint32_t)((lane >> 3) & 1) << 4;
    uint32_t baseB[2];
    #pragma unroll
    for (int p = 0; p < 2; ++p) {
        int r = nb + p * 16 + grpRowB;
        baseB[p] = (smem_base + A_STAGE_BYTES + r * 128 + ((r & 7) << 4)) ^ bKbit;
    }

    uint32_t acc[4][4][2];                   // f16x2 accumulators
    #pragma unroll
    for (int mi = 0; mi < 4; ++mi)
        #pragma unroll
        for (int ni = 0; ni < 4; ++ni) {
            acc[mi][ni][0] = 0u;
            acc[mi][ni][1] = 0u;
        }

    load_stage(smem_base, 0, 0, gA, gB, tid);
    load_stage(smem_base, 1, 1, gA, gB, tid);

    uint32_t a[2][4][4], b[2][4][2];         // double-buffered fragments
    int st = 0;

    for (int k = 0; k < NCHUNK; ++k) {
        uint32_t stOff = st * STAGE_BYTES;
        asm volatile("cp.async.wait_group 1;");
        __syncthreads();

        // prefetch kstep 0 fragments
        #pragma unroll
        for (int mi = 0; mi < 4; ++mi)
            LDSM4(a[0][mi][0], a[0][mi][1], a[0][mi][2], a[0][mi][3], baseA[mi] + stOff);
        #pragma unroll
        for (int p = 0; p < 2; ++p)
            LDSM4(b[0][2*p][0], b[0][2*p][1], b[0][2*p+1][0], b[0][2*p+1][1],
                  baseB[p] + stOff);

        // issue next gmem stage while fragments are in flight
        if (k + NSTAGE - 1 < NCHUNK) {
            int ns = st + 2; if (ns >= NSTAGE) ns -= NSTAGE;
            load_stage(smem_base, ns, k + NSTAGE - 1, gA, gB, tid);
        } else {
            asm volatile("cp.async.commit_group;");   // keep group count stable
        }

        #pragma unroll
        for (int ki = 0; ki < 4; ++ki) {
            int cur = ki & 1, nxt = cur ^ 1;
            if (ki < 3) {                              // prefetch kstep ki+1
                uint32_t kx = (uint32_t)(ki + 1) << 5;
                #pragma unroll
                for (int mi = 0; mi < 4; ++mi)
                    LDSM4(a[nxt][mi][0], a[nxt][mi][1], a[nxt][mi][2], a[nxt][mi][3],
                          (baseA[mi] + stOff) ^ kx);
                #pragma unroll
                for (int p = 0; p < 2; ++p)
                    LDSM4(b[nxt][2*p][0], b[nxt][2*p][1], b[nxt][2*p+1][0], b[nxt][2*p+1][1],
                          (baseB[p] + stOff) ^ kx);
            }
            #pragma unroll
            for (int mi = 0; mi < 4; ++mi)
                #pragma unroll
                for (int ni = 0; ni < 4; ++ni) {
                    uint32_t* c = acc[mi][ni];
                    asm volatile(
                        "mma.sync.aligned.m16n8k16.row.col.f16.f16.f16.f16 "
                        "{%0,%1}, {%2,%3,%4,%5}, {%6,%7}, {%0,%1};"
                        : "+r"(c[0]), "+r"(c[1])
                        : "r"(a[cur][mi][0]), "r"(a[cur][mi][1]),
                          "r"(a[cur][mi][2]), "r"(a[cur][mi][3]),
                          "r"(b[cur][ni][0]), "r"(b[cur][ni][1]));
                }
        }
        if (++st == NSTAGE) st = 0;
    }

    // ---- epilogue: per-row max of this 128x128 tile ----
    __syncthreads();
    if (tid < BM) smax[tid] = 0u;
    __syncthreads();

    #pragma unroll
    for (int mi = 0; mi < 4; ++mi) {
        __half2 h0 = __float2half2_rn(-60000.0f);
        __half2 h1 = __float2half2_rn(-60000.0f);
        #pragma unroll
        for (int ni = 0; ni < 4; ++ni) {
            h0 = __hmax2(h0, *(__half2*)&acc[mi][ni][0]);   // row = mb+mi*16+lane/4
            h1 = __hmax2(h1, *(__half2*)&acc[mi][ni][1]);   // row + 8
        }
        float m0 = fmaxf(__low2float(h0), __high2float(h0));
        float m1 = fmaxf(__low2float(h1), __high2float(h1));
        m0 = fmaxf(m0, __shfl_xor_sync(0xffffffffu, m0, 1));
        m0 = fmaxf(m0, __shfl_xor_sync(0xffffffffu, m0, 2));
        m1 = fmaxf(m1, __shfl_xor_sync(0xffffffffu, m1, 1));
        m1 = fmaxf(m1, __shfl_xor_sync(0xffffffffu, m1, 2));
        if ((lane & 3) == 0) {
            int r = mb + mi * 16 + (lane >> 2);
            atomicMax(&smax[r], fkey(m0));
            atomicMax(&smax[r + 8], fkey(m1));
        }
    }
    __syncthreads();
    if (tid < BM) atomicMax(&g_rowmax[tileM * BM + tid], smax[tid]);
}

// ---------------- final: loss = mean(1 - rowmax) ----------------
__global__ void final_reduce_kernel(float* __restrict__ out) {
    __shared__ float red[256];
    int tid = threadIdx.x;
    float s = 0.f;
    for (int i = tid; i < N_DIM; i += 256) {
        unsigned int key = g_rowmax[i];
        float f = (key & 0x80000000u) ? __uint_as_float(key & 0x7FFFFFFFu)
                                      : __uint_as_float(~key);
        s += 1.0f - f;
    }
    red[tid] = s;
    __syncthreads();
    for (int off = 128; off > 0; off >>= 1) {
        if (tid < off) red[tid] += red[tid + off];
        __syncthreads();
    }
    if (tid == 0) out[0] = red[0] / (float)N_DIM;
}

// ---------------- launch ----------------
extern "C" void kernel_launch(void* const* d_in, const int* in_sizes, int n_in,
                              void* d_out, int out_size) {
    const float* F_r = (const float*)d_in[0];
    const float* F_s = (const float*)d_in[1];

    cudaFuncSetAttribute(nnfm_gemm_hmma, cudaFuncAttributeMaxDynamicSharedMemorySize, SMEM_TOTAL);

    init_rowmax_kernel<<<N_DIM / 256, 256>>>();

    dim3 cg(N_DIM / 256, 4);
    colnorm_part_kernel<<<cg, 256>>>(F_r, 0);
    colnorm_part_kernel<<<cg, 256>>>(F_s, 1);

    dim3 tg(N_DIM / 64, C_DIM / 64);   // 256 x 12
    transpose_scale_kernel<<<tg, 256>>>(F_r, 0);
    transpose_scale_kernel<<<tg, 256>>>(F_s, 1);

    dim3 gg(N_DIM / BN, N_DIM / BM);   // 128 x 128
    nnfm_gemm_hmma<<<gg, 256, SMEM_TOTAL>>>();

    final_reduce_kernel<<<1, 256>>>((float*)d_out);
}

// round 9
// speedup vs baseline: 1.2194x; 1.1235x over previous
#include <cuda_runtime.h>
#include <cuda_fp16.h>
#include <cstdint>

// Problem constants (1, 768, 128, 128)
#define C_DIM 768
#define N_DIM 16384

// ---------------- GEMM tiling (fp16 mma.sync, 2-stage, occ=2) ----------------
#define BM 128
#define BN 256
#define KC 64                 // K per chunk = 128 bytes/row
#define NCHUNK (C_DIM / KC)   // 12
#define NSTAGE 2

#define A_STAGE_BYTES (BM * 128)                       // 16384
#define STAGE_BYTES ((BM + BN) * 128)                  // 49152
#define SMAX_OFF (NSTAGE * STAGE_BYTES)                // 98304
#define SINV_OFF (SMAX_OFF + 512)
#define SMEM_TOTAL (SINV_OFF + BN * 4)                 // ~99.8KB -> 2 CTAs/SM

// ---------------- scratch (no allocations allowed) ----------------
__device__ __half g_A[(size_t)N_DIM * C_DIM];   // F_r^T fp16 (unnormalized), [n][c]
__device__ __half g_B[(size_t)N_DIM * C_DIM];   // F_s^T fp16 (unnormalized), [m][c]
__device__ float g_invA[N_DIM];                 // 1/norm of g_A rows
__device__ float g_invB[N_DIM];                 // 1/norm of g_B rows
__device__ unsigned int g_rowmax[N_DIM];        // monotonic float keys of max(dot*invB)

__device__ __forceinline__ unsigned int fkey(float f) {
    unsigned int u = __float_as_uint(f);
    return (u & 0x80000000u) ? ~u : (u | 0x80000000u);
}
__device__ __forceinline__ uint32_t smem_u32(const void* p) {
    return (uint32_t)__cvta_generic_to_shared(p);
}

#define LDSM4(r0, r1, r2, r3, addr) \
    asm volatile("ldmatrix.sync.aligned.m8n8.x4.shared.b16 {%0,%1,%2,%3}, [%4];" \
                 : "=r"(r0), "=r"(r1), "=r"(r2), "=r"(r3) : "r"(addr))

// ---------------- init row maxes ----------------
__global__ void init_rowmax_kernel() {
    int i = blockIdx.x * blockDim.x + threadIdx.x;
    if (i < N_DIM) g_rowmax[i] = 0u;
}

// -------- transpose + fp16 convert (no normalization): [C][N] -> [N][C] ----------
__global__ void __launch_bounds__(256) transpose_kernel(const float* __restrict__ X,
                                                        int which) {
    __shared__ float tf[64][65];
    __half* T = which ? g_B : g_A;
    int n0 = blockIdx.x * 64;
    int c0 = blockIdx.y * 64;
    int t = threadIdx.x;

    #pragma unroll
    for (int i = 0; i < 4; ++i) {
        int idx = i * 256 + t;
        int row = idx >> 4;            // c offset 0..63
        int v4 = idx & 15;             // float4 index within row
        float4 v = *(const float4*)(X + (size_t)(c0 + row) * N_DIM + n0 + v4 * 4);
        tf[row][v4 * 4 + 0] = v.x;
        tf[row][v4 * 4 + 1] = v.y;
        tf[row][v4 * 4 + 2] = v.z;
        tf[row][v4 * 4 + 3] = v.w;
    }
    __syncthreads();

    #pragma unroll
    for (int j = 0; j < 8; ++j) {
        int idx = j * 256 + t;
        int nn = idx >> 5;             // n offset 0..63
        int p = idx & 31;              // fp16 pair within the 64 c's
        __half2 h = __floats2half2_rn(tf[2 * p][nn], tf[2 * p + 1][nn]);
        *(__half2*)(T + (size_t)(n0 + nn) * C_DIM + c0 + 2 * p) = h;
    }
}

// ---- row norms from the fp16 matrices (row-major -> coalesced along C) ----
__global__ void __launch_bounds__(256) colnorm16_kernel(int which) {
    const __half2* T2 = (const __half2*)(which ? g_B : g_A);
    float* inv = which ? g_invB : g_invA;
    int warp = threadIdx.x >> 5;
    int lane = threadIdx.x & 31;
    int row = blockIdx.x * 8 + warp;
    const __half2* p = T2 + (size_t)row * (C_DIM / 2);
    float s = 0.f;
    #pragma unroll
    for (int i = 0; i < 12; ++i) {
        float2 f = __half22float2(p[i * 32 + lane]);
        s += f.x * f.x + f.y * f.y;
    }
    #pragma unroll
    for (int d = 16; d > 0; d >>= 1) s += __shfl_xor_sync(0xffffffffu, s, d);
    if (lane == 0) inv[row] = 1.0f / fmaxf(sqrtf(s), 1e-12f);
}

// ---------------- fused GEMM + row-max (scaled by invB in epilogue) ----------------
// smem rows of 128B; 16B chunk ch swizzled: off = row*128 + ((ch ^ (row&7)) << 4)
__device__ __forceinline__ void load_stage(uint32_t smem_base, int stage, int chunk,
                                           const __half* gA,
                                           const __half* gB, int tid) {
    uint32_t sA = smem_base + stage * STAGE_BYTES;
    uint32_t sB = sA + A_STAGE_BYTES;
    const __half* srcA = gA + chunk * KC;
    const __half* srcB = gB + chunk * KC;
    #pragma unroll
    for (int i = 0; i < 4; ++i) {            // A: 128 rows x 8 chunks = 1024
        int c = i * 256 + tid;
        int row = c >> 3, ch = c & 7;
        uint32_t off = row * 128 + ((ch ^ (row & 7)) << 4);
        const __half* p = srcA + (size_t)row * C_DIM + ch * 8;
        asm volatile("cp.async.cg.shared.global [%0], [%1], 16;" :: "r"(sA + off), "l"(p));
    }
    #pragma unroll
    for (int i = 0; i < 8; ++i) {            // B: 256 rows x 8 chunks = 2048
        int c = i * 256 + tid;
        int row = c >> 3, ch = c & 7;
        uint32_t off = row * 128 + ((ch ^ (row & 7)) << 4);
        const __half* p = srcB + (size_t)row * C_DIM + ch * 8;
        asm volatile("cp.async.cg.shared.global [%0], [%1], 16;" :: "r"(sB + off), "l"(p));
    }
    asm volatile("cp.async.commit_group;");
}

__global__ void __launch_bounds__(256, 2) nnfm_gemm_hmma() {
    extern __shared__ __align__(1024) char smem[];
    uint32_t smem_base = smem_u32(smem);
    unsigned int* smax = (unsigned int*)(smem + SMAX_OFF);
    float* sInv = (float*)(smem + SINV_OFF);

    int tid = threadIdx.x;
    int wid = tid >> 5;
    int lane = tid & 31;
    int tileM = blockIdx.y, tileN = blockIdx.x;

    const __half* gA = g_A + (size_t)tileM * BM * C_DIM;
    const __half* gB = g_B + (size_t)tileN * BN * C_DIM;

    // warp grid: 2 (M) x 4 (N); warp tile 64x64 = 4x8 frags of m16n8
    int mb = (wid >> 2) * 64;
    int nb = (wid & 3) * 64;

    // ldmatrix lane addresses with swizzle folded
    int grpRowA = (lane & 7) + ((lane >> 3) & 1) * 8;
    uint32_t aKbit = (uint32_t)(lane >> 4) << 4;
    uint32_t baseA[4];
    #pragma unroll
    for (int mi = 0; mi < 4; ++mi) {
        int r = mb + mi * 16 + grpRowA;
        baseA[mi] = (smem_base + r * 128 + ((r & 7) << 4)) ^ aKbit;
    }
    int grpRowB = (lane & 7) + ((lane >> 4) << 3);
    uint32_t bKbit = (uint32_t)((lane >> 3) & 1) << 4;
    uint32_t baseB[4];
    #pragma unroll
    for (int p = 0; p < 4; ++p) {
        int r = nb + p * 16 + grpRowB;
        baseB[p] = (smem_base + A_STAGE_BYTES + r * 128 + ((r & 7) << 4)) ^ bKbit;
    }

    uint32_t acc[4][8][2];                   // f16x2 accumulators
    #pragma unroll
    for (int mi = 0; mi < 4; ++mi)
        #pragma unroll
        for (int ni = 0; ni < 8; ++ni) {
            acc[mi][ni][0] = 0u;
            acc[mi][ni][1] = 0u;
        }

    load_stage(smem_base, 0, 0, gA, gB, tid);
    load_stage(smem_base, 1, 1, gA, gB, tid);

    for (int k = 0; k < NCHUNK; ++k) {
        uint32_t stOff = (k & 1) * STAGE_BYTES;
        asm volatile("cp.async.wait_group 1;");
        __syncthreads();

        #pragma unroll
        for (int ki = 0; ki < 4; ++ki) {
            uint32_t kx = (uint32_t)ki << 5;
            uint32_t a[4][4], b[8][2];
            #pragma unroll
            for (int mi = 0; mi < 4; ++mi)
                LDSM4(a[mi][0], a[mi][1], a[mi][2], a[mi][3], (baseA[mi] + stOff) ^ kx);
            #pragma unroll
            for (int p = 0; p < 4; ++p)
                LDSM4(b[2*p][0], b[2*p][1], b[2*p+1][0], b[2*p+1][1],
                      (baseB[p] + stOff) ^ kx);
            #pragma unroll
            for (int mi = 0; mi < 4; ++mi)
                #pragma unroll
                for (int ni = 0; ni < 8; ++ni) {
                    uint32_t* c = acc[mi][ni];
                    asm volatile(
                        "mma.sync.aligned.m16n8k16.row.col.f16.f16.f16.f16 "
                        "{%0,%1}, {%2,%3,%4,%5}, {%6,%7}, {%0,%1};"
                        : "+r"(c[0]), "+r"(c[1])
                        : "r"(a[mi][0]), "r"(a[mi][1]), "r"(a[mi][2]), "r"(a[mi][3]),
                          "r"(b[ni][0]), "r"(b[ni][1]));
                }
        }
        __syncthreads();                         // stage fully consumed
        if (k + NSTAGE < NCHUNK)
            load_stage(smem_base, k & 1, k + NSTAGE, gA, gB, tid);
        else
            asm volatile("cp.async.commit_group;");   // keep group count stable
    }

    // ---- epilogue: per-row max of (dot * invB[col]) over this 128x256 tile ----
    if (tid < BM) smax[tid] = 0u;
    sInv[tid] = g_invB[tileN * BN + tid];
    __syncthreads();

    #pragma unroll
    for (int mi = 0; mi < 4; ++mi) {
        float m0 = -3.402823466e38f, m1 = -3.402823466e38f;
        #pragma unroll
        for (int ni = 0; ni < 8; ++ni) {
            int c = nb + ni * 8 + (lane & 3) * 2;
            float ivx = sInv[c], ivy = sInv[c + 1];
            float2 f0 = __half22float2(*(__half2*)&acc[mi][ni][0]);  // row = mb+mi*16+lane/4
            float2 f1 = __half22float2(*(__half2*)&acc[mi][ni][1]);  // row + 8
            m0 = fmaxf(m0, fmaxf(f0.x * ivx, f0.y * ivy));
            m1 = fmaxf(m1, fmaxf(f1.x * ivx, f1.y * ivy));
        }
        m0 = fmaxf(m0, __shfl_xor_sync(0xffffffffu, m0, 1));
        m0 = fmaxf(m0, __shfl_xor_sync(0xffffffffu, m0, 2));
        m1 = fmaxf(m1, __shfl_xor_sync(0xffffffffu, m1, 1));
        m1 = fmaxf(m1, __shfl_xor_sync(0xffffffffu, m1, 2));
        if ((lane & 3) == 0) {
            int r = mb + mi * 16 + (lane >> 2);
            atomicMax(&smax[r], fkey(m0));
            atomicMax(&smax[r + 8], fkey(m1));
        }
    }
    __syncthreads();
    if (tid < BM) atomicMax(&g_rowmax[tileM * BM + tid], smax[tid]);
}

// ---------------- final: loss = mean(1 - invA[n] * rowmax[n]) ----------------
__global__ void final_reduce_kernel(float* __restrict__ out) {
    __shared__ float red[256];
    int tid = threadIdx.x;
    float s = 0.f;
    for (int i = tid; i < N_DIM; i += 256) {
        unsigned int key = g_rowmax[i];
        float f = (key & 0x80000000u) ? __uint_as_float(key & 0x7FFFFFFFu)
                                      : __uint_as_float(~key);
        s += 1.0f - g_invA[i] * f;
    }
    red[tid] = s;
    __syncthreads();
    for (int off = 128; off > 0; off >>= 1) {
        if (tid < off) red[tid] += red[tid + off];
        __syncthreads();
    }
    if (tid == 0) out[0] = red[0] / (float)N_DIM;
}

// ---------------- launch ----------------
extern "C" void kernel_launch(void* const* d_in, const int* in_sizes, int n_in,
                              void* d_out, int out_size) {
    const float* F_r = (const float*)d_in[0];
    const float* F_s = (const float*)d_in[1];

    cudaFuncSetAttribute(nnfm_gemm_hmma, cudaFuncAttributeMaxDynamicSharedMemorySize, SMEM_TOTAL);

    init_rowmax_kernel<<<N_DIM / 256, 256>>>();

    dim3 tg(N_DIM / 64, C_DIM / 64);   // 256 x 12
    transpose_kernel<<<tg, 256>>>(F_r, 0);
    transpose_kernel<<<tg, 256>>>(F_s, 1);

    colnorm16_kernel<<<N_DIM / 8, 256>>>(0);
    colnorm16_kernel<<<N_DIM / 8, 256>>>(1);

    dim3 gg(N_DIM / BN, N_DIM / BM);   // 64 x 128
    nnfm_gemm_hmma<<<gg, 256, SMEM_TOTAL>>>();

    final_reduce_kernel<<<1, 256>>>((float*)d_out);
}

// round 10
// speedup vs baseline: 1.2219x; 1.0021x over previous
#include <cuda_runtime.h>
#include <cuda_fp16.h>
#include <cstdint>

// Problem constants (1, 768, 128, 128)
#define C_DIM 768
#define N_DIM 16384

// ---------------- GEMM tiling (fp16 mma.sync, 2-stage, occ=2) ----------------
#define BM 128
#define BN 256
#define KC 64                 // K per chunk = 128 bytes/row
#define NCHUNK (C_DIM / KC)   // 12
#define NSTAGE 2

#define A_STAGE_BYTES (BM * 128)                       // 16384
#define STAGE_BYTES ((BM + BN) * 128)                  // 49152
#define SMAX_OFF (NSTAGE * STAGE_BYTES)                // 98304
#define SINV_OFF (SMAX_OFF + 512)
#define SMEM_TOTAL (SINV_OFF + BN * 4)                 // ~99.8KB -> 2 CTAs/SM

// ---------------- scratch (no allocations allowed) ----------------
__device__ __half g_A[(size_t)N_DIM * C_DIM];   // F_r^T fp16 (unnormalized), [n][c]
__device__ __half g_B[(size_t)N_DIM * C_DIM];   // F_s^T fp16 (unnormalized), [m][c]
__device__ float g_invA[N_DIM];                 // 1/norm of g_A rows
__device__ float g_invB[N_DIM];                 // 1/norm of g_B rows
__device__ unsigned int g_rowmax[N_DIM];        // monotonic float keys of max(dot*invB)

__device__ __forceinline__ unsigned int fkey(float f) {
    unsigned int u = __float_as_uint(f);
    return (u & 0x80000000u) ? ~u : (u | 0x80000000u);
}
__device__ __forceinline__ uint32_t smem_u32(const void* p) {
    return (uint32_t)__cvta_generic_to_shared(p);
}

#define LDSM4(r0, r1, r2, r3, addr) \
    asm volatile("ldmatrix.sync.aligned.m8n8.x4.shared.b16 {%0,%1,%2,%3}, [%4];" \
                 : "=r"(r0), "=r"(r1), "=r"(r2), "=r"(r3) : "r"(addr))

// ---------------- init row maxes ----------------
__global__ void init_rowmax_kernel() {
    int i = blockIdx.x * blockDim.x + threadIdx.x;
    if (i < N_DIM) g_rowmax[i] = 0u;
}

// -------- transpose + fp16 convert (no normalization): [C][N] -> [N][C] ----------
__global__ void __launch_bounds__(256) transpose_kernel(const float* __restrict__ X,
                                                        int which) {
    __shared__ float tf[64][65];
    __half* T = which ? g_B : g_A;
    int n0 = blockIdx.x * 64;
    int c0 = blockIdx.y * 64;
    int t = threadIdx.x;

    #pragma unroll
    for (int i = 0; i < 4; ++i) {
        int idx = i * 256 + t;
        int row = idx >> 4;            // c offset 0..63
        int v4 = idx & 15;             // float4 index within row
        float4 v = *(const float4*)(X + (size_t)(c0 + row) * N_DIM + n0 + v4 * 4);
        tf[row][v4 * 4 + 0] = v.x;
        tf[row][v4 * 4 + 1] = v.y;
        tf[row][v4 * 4 + 2] = v.z;
        tf[row][v4 * 4 + 3] = v.w;
    }
    __syncthreads();

    #pragma unroll
    for (int j = 0; j < 8; ++j) {
        int idx = j * 256 + t;
        int nn = idx >> 5;             // n offset 0..63
        int p = idx & 31;              // fp16 pair within the 64 c's
        __half2 h = __floats2half2_rn(tf[2 * p][nn], tf[2 * p + 1][nn]);
        *(__half2*)(T + (size_t)(n0 + nn) * C_DIM + c0 + 2 * p) = h;
    }
}

// ---- row norms from the fp16 matrices (row-major -> coalesced along C) ----
__global__ void __launch_bounds__(256) colnorm16_kernel(int which) {
    const __half2* T2 = (const __half2*)(which ? g_B : g_A);
    float* inv = which ? g_invB : g_invA;
    int warp = threadIdx.x >> 5;
    int lane = threadIdx.x & 31;
    int row = blockIdx.x * 8 + warp;
    const __half2* p = T2 + (size_t)row * (C_DIM / 2);
    float s = 0.f;
    #pragma unroll
    for (int i = 0; i < 12; ++i) {
        float2 f = __half22float2(p[i * 32 + lane]);
        s += f.x * f.x + f.y * f.y;
    }
    #pragma unroll
    for (int d = 16; d > 0; d >>= 1) s += __shfl_xor_sync(0xffffffffu, s, d);
    if (lane == 0) inv[row] = 1.0f / fmaxf(sqrtf(s), 1e-12f);
}

// ---------------- fused GEMM + row-max (scaled by invB in epilogue) ----------------
// smem rows of 128B; 16B chunk ch swizzled: off = row*128 + ((ch ^ (row&7)) << 4)
__device__ __forceinline__ void load_stage(uint32_t smem_base, int stage, int chunk,
                                           const __half* gA,
                                           const __half* gB, int tid) {
    uint32_t sA = smem_base + stage * STAGE_BYTES;
    uint32_t sB = sA + A_STAGE_BYTES;
    const __half* srcA = gA + chunk * KC;
    const __half* srcB = gB + chunk * KC;
    #pragma unroll
    for (int i = 0; i < 4; ++i) {            // A: 128 rows x 8 chunks = 1024
        int c = i * 256 + tid;
        int row = c >> 3, ch = c & 7;
        uint32_t off = row * 128 + ((ch ^ (row & 7)) << 4);
        const __half* p = srcA + (size_t)row * C_DIM + ch * 8;
        asm volatile("cp.async.cg.shared.global [%0], [%1], 16;" :: "r"(sA + off), "l"(p));
    }
    #pragma unroll
    for (int i = 0; i < 8; ++i) {            // B: 256 rows x 8 chunks = 2048
        int c = i * 256 + tid;
        int row = c >> 3, ch = c & 7;
        uint32_t off = row * 128 + ((ch ^ (row & 7)) << 4);
        const __half* p = srcB + (size_t)row * C_DIM + ch * 8;
        asm volatile("cp.async.cg.shared.global [%0], [%1], 16;" :: "r"(sB + off), "l"(p));
    }
    asm volatile("cp.async.commit_group;");
}

__global__ void __launch_bounds__(256, 2) nnfm_gemm_hmma() {
    extern __shared__ __align__(1024) char smem[];
    uint32_t smem_base = smem_u32(smem);
    unsigned int* smax = (unsigned int*)(smem + SMAX_OFF);
    float* sInv = (float*)(smem + SINV_OFF);

    int tid = threadIdx.x;
    int wid = tid >> 5;
    int lane = tid & 31;
    int tileM = blockIdx.y, tileN = blockIdx.x;

    const __half* gA = g_A + (size_t)tileM * BM * C_DIM;
    const __half* gB = g_B + (size_t)tileN * BN * C_DIM;

    // warp grid: 2 (M) x 4 (N); warp tile 64x64 = 4x8 frags of m16n8
    int mb = (wid >> 2) * 64;
    int nb = (wid & 3) * 64;

    // ldmatrix lane addresses with swizzle folded
    int grpRowA = (lane & 7) + ((lane >> 3) & 1) * 8;
    uint32_t aKbit = (uint32_t)(lane >> 4) << 4;
    uint32_t baseA[4];
    #pragma unroll
    for (int mi = 0; mi < 4; ++mi) {
        int r = mb + mi * 16 + grpRowA;
        baseA[mi] = (smem_base + r * 128 + ((r & 7) << 4)) ^ aKbit;
    }
    int grpRowB = (lane & 7) + ((lane >> 4) << 3);
    uint32_t bKbit = (uint32_t)((lane >> 3) & 1) << 4;
    uint32_t baseB[4];
    #pragma unroll
    for (int p = 0; p < 4; ++p) {
        int r = nb + p * 16 + grpRowB;
        baseB[p] = (smem_base + A_STAGE_BYTES + r * 128 + ((r & 7) << 4)) ^ bKbit;
    }

    uint32_t acc[4][8][2];                   // f16x2 accumulators
    #pragma unroll
    for (int mi = 0; mi < 4; ++mi)
        #pragma unroll
        for (int ni = 0; ni < 8; ++ni) {
            acc[mi][ni][0] = 0u;
            acc[mi][ni][1] = 0u;
        }

    load_stage(smem_base, 0, 0, gA, gB, tid);
    load_stage(smem_base, 1, 1, gA, gB, tid);

    for (int k = 0; k < NCHUNK; ++k) {
        uint32_t stOff = (k & 1) * STAGE_BYTES;
        asm volatile("cp.async.wait_group 1;");
        __syncthreads();

        #pragma unroll
        for (int ki = 0; ki < 4; ++ki) {
            uint32_t kx = (uint32_t)ki << 5;
            uint32_t a[4][4], b[8][2];
            #pragma unroll
            for (int mi = 0; mi < 4; ++mi)
                LDSM4(a[mi][0], a[mi][1], a[mi][2], a[mi][3], (baseA[mi] + stOff) ^ kx);
            #pragma unroll
            for (int p = 0; p < 4; ++p)
                LDSM4(b[2*p][0], b[2*p][1], b[2*p+1][0], b[2*p+1][1],
                      (baseB[p] + stOff) ^ kx);
            #pragma unroll
            for (int mi = 0; mi < 4; ++mi)
                #pragma unroll
                for (int ni = 0; ni < 8; ++ni) {
                    uint32_t* c = acc[mi][ni];
                    asm volatile(
                        "mma.sync.aligned.m16n8k16.row.col.f16.f16.f16.f16 "
                        "{%0,%1}, {%2,%3,%4,%5}, {%6,%7}, {%0,%1};"
                        : "+r"(c[0]), "+r"(c[1])
                        : "r"(a[mi][0]), "r"(a[mi][1]), "r"(a[mi][2]), "r"(a[mi][3]),
                          "r"(b[ni][0]), "r"(b[ni][1]));
                }
        }
        __syncthreads();                         // stage fully consumed
        if (k + NSTAGE < NCHUNK)
            load_stage(smem_base, k & 1, k + NSTAGE, gA, gB, tid);
        else
            asm volatile("cp.async.commit_group;");   // keep group count stable
    }

    // ---- epilogue: per-row max of (dot * invB[col]) over this 128x256 tile ----
    if (tid < BM) smax[tid] = 0u;
    sInv[tid] = g_invB[tileN * BN + tid];
    __syncthreads();

    #pragma unroll
    for (int mi = 0; mi < 4; ++mi) {
        float m0 = -3.402823466e38f, m1 = -3.402823466e38f;
        #pragma unroll
        for (int ni = 0; ni < 8; ++ni) {
            int c = nb + ni * 8 + (lane & 3) * 2;
            float ivx = sInv[c], ivy = sInv[c + 1];
            float2 f0 = __half22float2(*(__half2*)&acc[mi][ni][0]);  // row = mb+mi*16+lane/4
            float2 f1 = __half22float2(*(__half2*)&acc[mi][ni][1]);  // row + 8
            m0 = fmaxf(m0, fmaxf(f0.x * ivx, f0.y * ivy));
            m1 = fmaxf(m1, fmaxf(f1.x * ivx, f1.y * ivy));
        }
        m0 = fmaxf(m0, __shfl_xor_sync(0xffffffffu, m0, 1));
        m0 = fmaxf(m0, __shfl_xor_sync(0xffffffffu, m0, 2));
        m1 = fmaxf(m1, __shfl_xor_sync(0xffffffffu, m1, 1));
        m1 = fmaxf(m1, __shfl_xor_sync(0xffffffffu, m1, 2));
        if ((lane & 3) == 0) {
            int r = mb + mi * 16 + (lane >> 2);
            atomicMax(&smax[r], fkey(m0));
            atomicMax(&smax[r + 8], fkey(m1));
        }
    }
    __syncthreads();
    if (tid < BM) atomicMax(&g_rowmax[tileM * BM + tid], smax[tid]);
}

// ---------------- final: loss = mean(1 - invA[n] * rowmax[n]) ----------------
__global__ void final_reduce_kernel(float* __restrict__ out) {
    __shared__ float red[256];
    int tid = threadIdx.x;
    float s = 0.f;
    for (int i = tid; i < N_DIM; i += 256) {
        unsigned int key = g_rowmax[i];
        float f = (key & 0x80000000u) ? __uint_as_float(key & 0x7FFFFFFFu)
                                      : __uint_as_float(~key);
        s += 1.0f - g_invA[i] * f;
    }
    red[tid] = s;
    __syncthreads();
    for (int off = 128; off > 0; off >>= 1) {
        if (tid < off) red[tid] += red[tid + off];
        __syncthreads();
    }
    if (tid == 0) out[0] = red[0] / (float)N_DIM;
}

// ---------------- launch ----------------
extern "C" void kernel_launch(void* const* d_in, const int* in_sizes, int n_in,
                              void* d_out, int out_size) {
    const float* F_r = (const float*)d_in[0];
    const float* F_s = (const float*)d_in[1];

    cudaFuncSetAttribute(nnfm_gemm_hmma, cudaFuncAttributeMaxDynamicSharedMemorySize, SMEM_TOTAL);

    init_rowmax_kernel<<<N_DIM / 256, 256>>>();

    dim3 tg(N_DIM / 64, C_DIM / 64);   // 256 x 12
    transpose_kernel<<<tg, 256>>>(F_r, 0);
    transpose_kernel<<<tg, 256>>>(F_s, 1);

    colnorm16_kernel<<<N_DIM / 8, 256>>>(0);
    colnorm16_kernel<<<N_DIM / 8, 256>>>(1);

    dim3 gg(N_DIM / BN, N_DIM / BM);   // 64 x 128
    nnfm_gemm_hmma<<<gg, 256, SMEM_TOTAL>>>();

    final_reduce_kernel<<<1, 256>>>((float*)d_out);
}